// round 2
// baseline (speedup 1.0000x reference)
#include <cuda_runtime.h>

// Problem constants
#define BDIM 4
#define TDIM 4096
#define EMBD 768
#define HEAD 64
#define MROWS (BDIM * TDIM)   // 16384 total rows

// Scratch for projected Q, K, V (12 MB total) — __device__ globals (no allocs allowed)
__device__ float g_q[MROWS * HEAD];
__device__ float g_k[MROWS * HEAD];
__device__ float g_v[MROWS * HEAD];

// ---------------------------------------------------------------------------
// Packed fp32x2 helpers (sm_100+ PTX; 2 FMAs per lane per instruction)
// ---------------------------------------------------------------------------
typedef unsigned long long u64;

__device__ __forceinline__ u64 pk2(float lo, float hi) {
    u64 r; asm("mov.b64 %0, {%1,%2};" : "=l"(r) : "f"(lo), "f"(hi)); return r;
}
__device__ __forceinline__ u64 dup2(float x) { return pk2(x, x); }
__device__ __forceinline__ void unpk2(u64 v, float& lo, float& hi) {
    asm("mov.b64 {%0,%1}, %2;" : "=f"(lo), "=f"(hi) : "l"(v));
}
__device__ __forceinline__ u64 fma2(u64 a, u64 b, u64 c) {
    u64 d; asm("fma.rn.f32x2 %0, %1, %2, %3;" : "=l"(d) : "l"(a), "l"(b), "l"(c)); return d;
}
__device__ __forceinline__ u64 mul2(u64 a, u64 b) {
    u64 d; asm("mul.rn.f32x2 %0, %1, %2;" : "=l"(d) : "l"(a), "l"(b)); return d;
}

// ---------------------------------------------------------------------------
// Projection kernel: out[m, h] = sum_k x[m, k] * W[k, h]
// Grid: (128 M-tiles, 3 matrices). Block: 256 threads.
// Tile: 128 rows x 64 cols, K-step 16. Thread micro-tile: 4 rows x 8 cols.
// ---------------------------------------------------------------------------
__global__ void __launch_bounds__(256) proj_kernel(
    const float* __restrict__ x,
    const float* __restrict__ Wq,
    const float* __restrict__ Wk,
    const float* __restrict__ Wv)
{
    __shared__ __align__(16) float As[128][16];
    __shared__ __align__(16) float Ws[16][64];

    const int z = blockIdx.y;
    const float* W = (z == 0) ? Wq : (z == 1) ? Wk : Wv;
    float* outp    = (z == 0) ? g_q : (z == 1) ? g_k : g_v;

    const int m0  = blockIdx.x * 128;
    const int tid = threadIdx.x;
    const int tr  = tid >> 3;   // 0..31 : row group (4 rows each)
    const int tc  = tid & 7;    // 0..7  : col group (8 cols each)

    u64 acc[4][4];
    #pragma unroll
    for (int i = 0; i < 4; i++)
        #pragma unroll
        for (int p = 0; p < 4; p++) acc[i][p] = 0ULL;

    for (int k0 = 0; k0 < EMBD; k0 += 16) {
        __syncthreads();
        // Load x tile: 128 x 16 floats = 512 float4
        #pragma unroll
        for (int u = 0; u < 2; u++) {
            int idx = tid + u * 256;
            int row = idx >> 2, kq = idx & 3;
            float4 v = *(const float4*)&x[(m0 + row) * EMBD + k0 + kq * 4];
            *(float4*)&As[row][kq * 4] = v;
        }
        // Load W tile: 16 x 64 floats = 256 float4
        {
            int row = tid >> 4, cq = tid & 15;
            *(float4*)&Ws[row][cq * 4] = *(const float4*)&W[(k0 + row) * HEAD + cq * 4];
        }
        __syncthreads();

        #pragma unroll
        for (int k = 0; k < 16; k++) {
            u64 a[4];
            #pragma unroll
            for (int i = 0; i < 4; i++) a[i] = dup2(As[tr * 4 + i][k]);
            u64 w[4];
            #pragma unroll
            for (int p = 0; p < 4; p++) w[p] = *(const u64*)&Ws[k][tc * 8 + p * 2];
            #pragma unroll
            for (int i = 0; i < 4; i++)
                #pragma unroll
                for (int p = 0; p < 4; p++)
                    acc[i][p] = fma2(a[i], w[p], acc[i][p]);
        }
    }

    // Store 4 rows x 8 cols per thread
    #pragma unroll
    for (int i = 0; i < 4; i++) {
        float o[8];
        #pragma unroll
        for (int p = 0; p < 4; p++) unpk2(acc[i][p], o[2 * p], o[2 * p + 1]);
        int row = m0 + tr * 4 + i;
        *(float4*)&outp[row * HEAD + tc * 8]     = make_float4(o[0], o[1], o[2], o[3]);
        *(float4*)&outp[row * HEAD + tc * 8 + 4] = make_float4(o[4], o[5], o[6], o[7]);
    }
}

// ---------------------------------------------------------------------------
// Flash-attention kernel (fp32, causal, online softmax).
// Grid: (32 q-tile pairs, B). Block: 256 threads.
// Each block handles q-tiles {p, 63-p}  ->  exactly 65 k-tile iterations.
// Tiles are 64 x 64. Thread micro-tile: 4 rows x 4 cols (16x16 thread grid).
// ---------------------------------------------------------------------------
struct SmemA {
    float Qs[64][66];
    float Ks[64][66];
    float Vs[64][66];
    float Ps[64][66];
    float m[64];
    float l[64];
    float alph[64];
};

__global__ void __launch_bounds__(256) attn_kernel(float* __restrict__ out)
{
    extern __shared__ __align__(16) char smraw[];
    SmemA& S = *reinterpret_cast<SmemA*>(smraw);

    const int b    = blockIdx.y;
    const int pair = blockIdx.x;       // 0..31
    const int tid  = threadIdx.x;
    const int tr   = tid >> 4;         // 0..15
    const int tc   = tid & 15;         // 0..15
    const int r0   = tr * 4;
    const int c0   = tc * 4;

    const float* qg = g_q + b * TDIM * HEAD;
    const float* kg = g_k + b * TDIM * HEAD;
    const float* vg = g_v + b * TDIM * HEAD;
    float*       og = out + b * TDIM * HEAD;

    for (int half = 0; half < 2; half++) {
        const int qt = half ? (63 - pair) : pair;

        __syncthreads();   // protect smem reuse across halves
        if (tid < 64) { S.m[tid] = -1e30f; S.l[tid] = 0.0f; }

        // Load Q tile, pre-scaled by 1/sqrt(HEAD) = 0.125
        #pragma unroll
        for (int u = 0; u < 4; u++) {
            int idx = tid + u * 256;               // 1024 float4
            int row = idx >> 4, cq = idx & 15;
            float4 v = *(const float4*)&qg[(qt * 64 + row) * HEAD + cq * 4];
            S.Qs[row][cq * 4 + 0] = v.x * 0.125f;
            S.Qs[row][cq * 4 + 1] = v.y * 0.125f;
            S.Qs[row][cq * 4 + 2] = v.z * 0.125f;
            S.Qs[row][cq * 4 + 3] = v.w * 0.125f;
        }

        u64 o2[4][2];
        #pragma unroll
        for (int i = 0; i < 4; i++) { o2[i][0] = 0ULL; o2[i][1] = 0ULL; }

        for (int kt = 0; kt <= qt; kt++) {
            __syncthreads();   // previous PV reads done before overwriting K/V
            // Load K and V tiles
            #pragma unroll
            for (int u = 0; u < 4; u++) {
                int idx = tid + u * 256;
                int row = idx >> 4, cq = idx & 15;
                float4 kv = *(const float4*)&kg[(kt * 64 + row) * HEAD + cq * 4];
                float4 vv = *(const float4*)&vg[(kt * 64 + row) * HEAD + cq * 4];
                S.Ks[row][cq * 4 + 0] = kv.x;  S.Ks[row][cq * 4 + 1] = kv.y;
                S.Ks[row][cq * 4 + 2] = kv.z;  S.Ks[row][cq * 4 + 3] = kv.w;
                S.Vs[row][cq * 4 + 0] = vv.x;  S.Vs[row][cq * 4 + 1] = vv.y;
                S.Vs[row][cq * 4 + 2] = vv.z;  S.Vs[row][cq * 4 + 3] = vv.w;
            }
            __syncthreads();

            // S = Q * K^T   (pack over the reduction dim d; combine halves after)
            u64 s2[4][4];
            #pragma unroll
            for (int i = 0; i < 4; i++)
                #pragma unroll
                for (int j = 0; j < 4; j++) s2[i][j] = 0ULL;

            #pragma unroll 8
            for (int d2 = 0; d2 < 32; d2++) {
                u64 qp[4], kp[4];
                #pragma unroll
                for (int i = 0; i < 4; i++) qp[i] = *(const u64*)&S.Qs[r0 + i][d2 * 2];
                #pragma unroll
                for (int j = 0; j < 4; j++) kp[j] = *(const u64*)&S.Ks[c0 + j][d2 * 2];
                #pragma unroll
                for (int i = 0; i < 4; i++)
                    #pragma unroll
                    for (int j = 0; j < 4; j++)
                        s2[i][j] = fma2(qp[i], kp[j], s2[i][j]);
            }

            // Combine pair halves, apply causal mask on the diagonal tile, stage to smem
            const bool diag = (kt == qt);
            #pragma unroll
            for (int i = 0; i < 4; i++) {
                #pragma unroll
                for (int j = 0; j < 4; j++) {
                    float lo, hi; unpk2(s2[i][j], lo, hi);
                    float s = lo + hi;
                    if (diag && (c0 + j > r0 + i)) s = -1e30f;
                    S.Ps[r0 + i][c0 + j] = s;
                }
            }
            __syncthreads();

            // Online softmax: 4 threads per row, 16 cols each
            {
                const int r  = tid >> 2;
                const int cb = (tid & 3) * 16;
                float mloc = -1e30f;
                #pragma unroll
                for (int t = 0; t < 16; t++) mloc = fmaxf(mloc, S.Ps[r][cb + t]);
                mloc = fmaxf(mloc, __shfl_xor_sync(0xffffffffu, mloc, 1));
                mloc = fmaxf(mloc, __shfl_xor_sync(0xffffffffu, mloc, 2));
                const float mold = S.m[r];
                const float mnew = fmaxf(mold, mloc);
                float ssum = 0.0f;
                #pragma unroll
                for (int t = 0; t < 16; t++) {
                    float p = __expf(S.Ps[r][cb + t] - mnew);
                    S.Ps[r][cb + t] = p;
                    ssum += p;
                }
                ssum += __shfl_xor_sync(0xffffffffu, ssum, 1);
                ssum += __shfl_xor_sync(0xffffffffu, ssum, 2);
                if ((tid & 3) == 0) {
                    const float alpha = __expf(mold - mnew);
                    S.m[r]    = mnew;
                    S.l[r]    = S.l[r] * alpha + ssum;
                    S.alph[r] = alpha;
                }
            }
            __syncthreads();

            // Rescale accumulators, then O += P * V
            #pragma unroll
            for (int i = 0; i < 4; i++) {
                u64 al = dup2(S.alph[r0 + i]);
                o2[i][0] = mul2(o2[i][0], al);
                o2[i][1] = mul2(o2[i][1], al);
            }
            #pragma unroll 8
            for (int j = 0; j < 64; j++) {
                u64 vp0 = *(const u64*)&S.Vs[j][c0];
                u64 vp1 = *(const u64*)&S.Vs[j][c0 + 2];
                #pragma unroll
                for (int i = 0; i < 4; i++) {
                    u64 pp = dup2(S.Ps[r0 + i][j]);
                    o2[i][0] = fma2(pp, vp0, o2[i][0]);
                    o2[i][1] = fma2(pp, vp1, o2[i][1]);
                }
            }
        }

        // Epilogue: out = O / l
        #pragma unroll
        for (int i = 0; i < 4; i++) {
            const float inv = 1.0f / S.l[r0 + i];
            float a0, a1, a2, a3;
            unpk2(o2[i][0], a0, a1);
            unpk2(o2[i][1], a2, a3);
            *(float4*)&og[(qt * 64 + r0 + i) * HEAD + c0] =
                make_float4(a0 * inv, a1 * inv, a2 * inv, a3 * inv);
        }
    }
}

// ---------------------------------------------------------------------------
// Entry point
// ---------------------------------------------------------------------------
extern "C" void kernel_launch(void* const* d_in, const int* in_sizes, int n_in,
                              void* d_out, int out_size)
{
    const float* x  = (const float*)d_in[0];
    const float* Wk = (const float*)d_in[1];
    const float* Wq = (const float*)d_in[2];
    const float* Wv = (const float*)d_in[3];
    float* out = (float*)d_out;

    (void)in_sizes; (void)n_in; (void)out_size;

    cudaFuncSetAttribute(attn_kernel, cudaFuncAttributeMaxDynamicSharedMemorySize,
                         (int)sizeof(SmemA));

    proj_kernel<<<dim3(128, 3), 256>>>(x, Wq, Wk, Wv);
    attn_kernel<<<dim3(32, BDIM), 256, sizeof(SmemA)>>>(out);
}

// round 12
// speedup vs baseline: 1.2547x; 1.2547x over previous
#include <cuda_runtime.h>

// Problem constants
#define BDIM 4
#define TDIM 4096
#define EMBD 768
#define HEAD 64
#define MROWS (BDIM * TDIM)

// Scratch for projected Q, K, V
__device__ float g_q[MROWS * HEAD];
__device__ float g_k[MROWS * HEAD];
__device__ float g_v[MROWS * HEAD];

typedef unsigned long long u64;

__device__ __forceinline__ u64 pk2(float lo, float hi) {
    u64 r; asm("mov.b64 %0, {%1,%2};" : "=l"(r) : "f"(lo), "f"(hi)); return r;
}
__device__ __forceinline__ u64 dup2(float x) { return pk2(x, x); }
__device__ __forceinline__ void unpk2(u64 v, float& lo, float& hi) {
    asm("mov.b64 {%0,%1}, %2;" : "=f"(lo), "=f"(hi) : "l"(v));
}
__device__ __forceinline__ u64 fma2(u64 a, u64 b, u64 c) {
    u64 d; asm("fma.rn.f32x2 %0, %1, %2, %3;" : "=l"(d) : "l"(a), "l"(b), "l"(c)); return d;
}
__device__ __forceinline__ u64 mul2(u64 a, u64 b) {
    u64 d; asm("mul.rn.f32x2 %0, %1, %2;" : "=l"(d) : "l"(a), "l"(b)); return d;
}

// ---------------------------------------------------------------------------
// Projection: out[m,h] = sum_k x[m,k] * W[k,h]
// Grid (128, 3), 256 threads. Tile 128x64, K-step 32.
// Micro-tile 4 rows x 8 cols; cols strided: c = 2*tc + 16*p (conflict-free W reads).
// As padded to 33 floats/row -> conflict-free column reads.
// ---------------------------------------------------------------------------
__global__ void __launch_bounds__(256) proj_kernel(
    const float* __restrict__ x,
    const float* __restrict__ Wq,
    const float* __restrict__ Wk,
    const float* __restrict__ Wv)
{
    __shared__ float As[128][33];
    __shared__ __align__(16) float Ws[32][64];

    const int z = blockIdx.y;
    const float* W = (z == 0) ? Wq : (z == 1) ? Wk : Wv;
    float* outp    = (z == 0) ? g_q : (z == 1) ? g_k : g_v;

    const int m0  = blockIdx.x * 128;
    const int tid = threadIdx.x;
    const int tr  = tid >> 3;   // 0..31 (4 rows each)
    const int tc  = tid & 7;    // 0..7  (8 strided cols each)

    u64 acc[4][4];
    #pragma unroll
    for (int i = 0; i < 4; i++)
        #pragma unroll
        for (int p = 0; p < 4; p++) acc[i][p] = 0ULL;

    for (int k0 = 0; k0 < EMBD; k0 += 32) {
        __syncthreads();
        // x tile: 128 x 32 = 1024 float4 (scalar stores into padded rows; conflict-free)
        #pragma unroll
        for (int u = 0; u < 4; u++) {
            int idx = tid + u * 256;
            int row = idx >> 3, kq = idx & 7;
            float4 v = *(const float4*)&x[(m0 + row) * EMBD + k0 + kq * 4];
            As[row][kq * 4 + 0] = v.x;  As[row][kq * 4 + 1] = v.y;
            As[row][kq * 4 + 2] = v.z;  As[row][kq * 4 + 3] = v.w;
        }
        // W tile: 32 x 64 = 512 float4
        #pragma unroll
        for (int u = 0; u < 2; u++) {
            int idx = tid + u * 256;
            int row = idx >> 4, cq = idx & 15;
            *(float4*)&Ws[row][cq * 4] = *(const float4*)&W[(k0 + row) * HEAD + cq * 4];
        }
        __syncthreads();

        #pragma unroll 8
        for (int k = 0; k < 32; k++) {
            u64 a[4];
            #pragma unroll
            for (int i = 0; i < 4; i++) a[i] = dup2(As[tr * 4 + i][k]);
            u64 w[4];
            #pragma unroll
            for (int p = 0; p < 4; p++) w[p] = *(const u64*)&Ws[k][tc * 2 + p * 16];
            #pragma unroll
            for (int i = 0; i < 4; i++)
                #pragma unroll
                for (int p = 0; p < 4; p++)
                    acc[i][p] = fma2(a[i], w[p], acc[i][p]);
        }
    }

    #pragma unroll
    for (int i = 0; i < 4; i++) {
        int row = m0 + tr * 4 + i;
        #pragma unroll
        for (int p = 0; p < 4; p++) {
            float lo, hi; unpk2(acc[i][p], lo, hi);
            *(float2*)&outp[row * HEAD + tc * 2 + p * 16] = make_float2(lo, hi);
        }
    }
}

// ---------------------------------------------------------------------------
// Flash attention (fp32, causal, online softmax) — conflict-free LDS edition.
// Grid 256 (64 q-tiles x B, largest-first), 256 threads, 2 blocks/SM target.
// Thread (tr 0..15, tc 0..15): rows r0..r0+3; QK key tokens jt = tc+16*js;
// PV/out cols {2tc,2tc+1, 2tc+32,2tc+33}. Softmax state in registers,
// row reductions via 16-lane shuffles. 3 syncthreads per k-tile.
// ---------------------------------------------------------------------------
struct SmemA {
    float Qs[64][66];
    float Ks[64][66];
    float Vs[64][66];
    float Ps[64][66];
};

__global__ void __launch_bounds__(256, 2) attn_kernel(float* __restrict__ out)
{
    extern __shared__ __align__(16) char smraw[];
    SmemA& S = *reinterpret_cast<SmemA*>(smraw);

    const int qi = blockIdx.x;          // 0..255
    const int qt = 63 - (qi >> 2);      // largest work first
    const int b  = qi & 3;
    const int tid = threadIdx.x;
    const int tr  = tid >> 4;           // 0..15
    const int tc  = tid & 15;           // 0..15
    const int r0  = tr * 4;

    const float* qg = g_q + b * TDIM * HEAD;
    const float* kg = g_k + b * TDIM * HEAD;
    const float* vg = g_v + b * TDIM * HEAD;
    float*       og = out + b * TDIM * HEAD;

    // Load Q tile (pre-scaled by 1/sqrt(64) = 0.125); float2 stores (pad 66 keeps 8B align)
    #pragma unroll
    for (int u = 0; u < 4; u++) {
        int idx = tid + u * 256;
        int row = idx >> 4, cq = idx & 15;
        float4 v = *(const float4*)&qg[(qt * 64 + row) * HEAD + cq * 4];
        *(float2*)&S.Qs[row][cq * 4]     = make_float2(v.x * 0.125f, v.y * 0.125f);
        *(float2*)&S.Qs[row][cq * 4 + 2] = make_float2(v.z * 0.125f, v.w * 0.125f);
    }

    float m_i[4], l_i[4];
    u64 o2[4][2];
    #pragma unroll
    for (int i = 0; i < 4; i++) {
        m_i[i] = -1e30f; l_i[i] = 0.0f;
        o2[i][0] = 0ULL; o2[i][1] = 0ULL;
    }

    for (int kt = 0; kt <= qt; kt++) {
        __syncthreads();   // prior PV reads of Ks/Vs/Ps complete
        #pragma unroll
        for (int u = 0; u < 4; u++) {
            int idx = tid + u * 256;
            int row = idx >> 4, cq = idx & 15;
            float4 kv = *(const float4*)&kg[(kt * 64 + row) * HEAD + cq * 4];
            float4 vv = *(const float4*)&vg[(kt * 64 + row) * HEAD + cq * 4];
            *(float2*)&S.Ks[row][cq * 4]     = make_float2(kv.x, kv.y);
            *(float2*)&S.Ks[row][cq * 4 + 2] = make_float2(kv.z, kv.w);
            *(float2*)&S.Vs[row][cq * 4]     = make_float2(vv.x, vv.y);
            *(float2*)&S.Vs[row][cq * 4 + 2] = make_float2(vv.z, vv.w);
        }
        __syncthreads();

        // ---- S = Q K^T : d-chunked, q in registers, conflict-free k loads ----
        u64 s2[4][4];
        #pragma unroll
        for (int i = 0; i < 4; i++)
            #pragma unroll
            for (int j = 0; j < 4; j++) s2[i][j] = 0ULL;

        #pragma unroll 2
        for (int dc = 0; dc < 8; dc++) {
            u64 qreg[4][4];
            #pragma unroll
            for (int i = 0; i < 4; i++)
                #pragma unroll
                for (int q2 = 0; q2 < 4; q2++)
                    qreg[i][q2] = *(const u64*)&S.Qs[r0 + i][dc * 8 + q2 * 2];
            #pragma unroll
            for (int d2 = 0; d2 < 4; d2++) {
                u64 kp[4];
                #pragma unroll
                for (int js = 0; js < 4; js++)
                    kp[js] = *(const u64*)&S.Ks[tc + 16 * js][dc * 8 + d2 * 2];
                #pragma unroll
                for (int i = 0; i < 4; i++)
                    #pragma unroll
                    for (int js = 0; js < 4; js++)
                        s2[i][js] = fma2(qreg[i][d2], kp[js], s2[i][js]);
            }
        }

        // ---- mask + online softmax (registers + 16-lane shuffles) ----
        const bool diag = (kt == qt);
        float p[4][4];
        #pragma unroll
        for (int i = 0; i < 4; i++) {
            float mloc = -1e30f;
            #pragma unroll
            for (int js = 0; js < 4; js++) {
                float lo, hi; unpk2(s2[i][js], lo, hi);
                float s = lo + hi;
                if (diag && (tc + 16 * js > r0 + i)) s = -1e30f;
                p[i][js] = s;
                mloc = fmaxf(mloc, s);
            }
            mloc = fmaxf(mloc, __shfl_xor_sync(0xffffffffu, mloc, 1));
            mloc = fmaxf(mloc, __shfl_xor_sync(0xffffffffu, mloc, 2));
            mloc = fmaxf(mloc, __shfl_xor_sync(0xffffffffu, mloc, 4));
            mloc = fmaxf(mloc, __shfl_xor_sync(0xffffffffu, mloc, 8));
            const float mnew = fmaxf(m_i[i], mloc);
            const float alpha = __expf(m_i[i] - mnew);
            m_i[i] = mnew;
            float rs = 0.0f;
            #pragma unroll
            for (int js = 0; js < 4; js++) {
                float e = __expf(p[i][js] - mnew);
                p[i][js] = e;
                rs += e;
            }
            rs += __shfl_xor_sync(0xffffffffu, rs, 1);
            rs += __shfl_xor_sync(0xffffffffu, rs, 2);
            rs += __shfl_xor_sync(0xffffffffu, rs, 4);
            rs += __shfl_xor_sync(0xffffffffu, rs, 8);
            l_i[i] = l_i[i] * alpha + rs;
            u64 al = dup2(alpha);
            o2[i][0] = mul2(o2[i][0], al);
            o2[i][1] = mul2(o2[i][1], al);
            #pragma unroll
            for (int js = 0; js < 4; js++)
                S.Ps[r0 + i][tc + 16 * js] = p[i][js];
        }
        __syncthreads();

        // ---- O += P V : t-chunked, p in registers, conflict-free v loads ----
        #pragma unroll 2
        for (int tcn = 0; tcn < 8; tcn++) {
            float pr[4][8];
            #pragma unroll
            for (int i = 0; i < 4; i++)
                #pragma unroll
                for (int t2 = 0; t2 < 4; t2++) {
                    float2 pp = *(const float2*)&S.Ps[r0 + i][tcn * 8 + t2 * 2];
                    pr[i][t2 * 2]     = pp.x;
                    pr[i][t2 * 2 + 1] = pp.y;
                }
            #pragma unroll
            for (int tt = 0; tt < 8; tt++) {
                int t = tcn * 8 + tt;
                u64 vp0 = *(const u64*)&S.Vs[t][tc * 2];
                u64 vp1 = *(const u64*)&S.Vs[t][tc * 2 + 32];
                #pragma unroll
                for (int i = 0; i < 4; i++) {
                    u64 pd = dup2(pr[i][tt]);
                    o2[i][0] = fma2(pd, vp0, o2[i][0]);
                    o2[i][1] = fma2(pd, vp1, o2[i][1]);
                }
            }
        }
    }

    // Epilogue: out = O / l  (cols {2tc, 2tc+32})
    #pragma unroll
    for (int i = 0; i < 4; i++) {
        const float inv = 1.0f / l_i[i];
        float a0, a1;
        unpk2(o2[i][0], a0, a1);
        *(float2*)&og[(qt * 64 + r0 + i) * HEAD + tc * 2] =
            make_float2(a0 * inv, a1 * inv);
        unpk2(o2[i][1], a0, a1);
        *(float2*)&og[(qt * 64 + r0 + i) * HEAD + tc * 2 + 32] =
            make_float2(a0 * inv, a1 * inv);
    }
}

// ---------------------------------------------------------------------------
// Entry point
// ---------------------------------------------------------------------------
extern "C" void kernel_launch(void* const* d_in, const int* in_sizes, int n_in,
                              void* d_out, int out_size)
{
    const float* x  = (const float*)d_in[0];
    const float* Wk = (const float*)d_in[1];
    const float* Wq = (const float*)d_in[2];
    const float* Wv = (const float*)d_in[3];
    float* out = (float*)d_out;

    (void)in_sizes; (void)n_in; (void)out_size;

    cudaFuncSetAttribute(attn_kernel, cudaFuncAttributeMaxDynamicSharedMemorySize,
                         (int)sizeof(SmemA));

    proj_kernel<<<dim3(128, 3), 256>>>(x, Wq, Wk, Wv);
    attn_kernel<<<256, 256, sizeof(SmemA)>>>(out);
}